// round 4
// baseline (speedup 1.0000x reference)
#include <cuda_runtime.h>
#include <math.h>

#define HH 496
#define WW 432
#define HW (HH*WW)            // 214272
#define APL 6
#define NANCH (HW*APL)        // 1285632
#define KPRE 4096
#define MAXN 500
#define SCORE_THR 0.1f
#define NMS_THR 0.5f
#define CAND_CAP (1<<18)
#define TIE_CAP 4096
#define PI_F 3.14159265358979323846f
#define PIH_F 1.57079632679489661923f

// ---------------- device scratch (static, no allocations) ----------------
__device__ unsigned g_key[NANCH];
__device__ unsigned g_hist[65536];
__device__ unsigned g_hist2[65536];
__device__ int g_cntHi;
__device__ int g_candCnt;
__device__ int g_tieCnt;
__device__ int g_thr1;
__device__ int g_k2;
__device__ unsigned g_cand_key[CAND_CAP];
__device__ int      g_cand_idx[CAND_CAP];
__device__ int      g_tie[TIE_CAP];
__device__ int      g_topk_idx[KPRE];
__device__ float    g_sc[KPRE*3];
__device__ float    g_dirf[KPRE];
__device__ float    g_box[KPRE*7];
__device__ float4   g_xyxy[KPRE];
__device__ int      g_sorted_slot[3*KPRE];
__device__ float    g_sorted_score[3*KPRE];
__device__ float4   g_sxy[3*KPRE];
__device__ int      g_kept_slot[3*MAXN];
__device__ float    g_kept_score[3*MAXN];
__device__ int      g_kept_cnt[3];

__device__ __forceinline__ float sigd(float x) {
    // double-rounded sigmoid: matches fp32 reference sigmoid to <=1ulp,
    // monotone (order-preserving) for selection
    return (float)(1.0 / (1.0 + exp(-(double)x)));
}

__device__ __forceinline__ float area_rn(float x1, float y1, float x2, float y2) {
    // ((x2 - x1) + 1) * ((y2 - y1) + 1) with per-op IEEE rounding (no FMA)
    return __fmul_rn(__fadd_rn(__fsub_rn(x2, x1), 1.f),
                     __fadd_rn(__fsub_rn(y2, y1), 1.f));
}

// ---------------- kernel 0: zero scratch ----------------
__global__ void zero_kernel() {
    int t = blockIdx.x * blockDim.x + threadIdx.x;
    if (t < 65536) { g_hist[t] = 0u; g_hist2[t] = 0u; }
    if (t == 0) { g_cntHi = 0; g_candCnt = 0; g_tieCnt = 0; }
}

// ---------------- kernel 1: per-anchor max-score key + histogram ----------------
__global__ void score_hist(const float* __restrict__ cls) {
    int s = blockIdx.x * blockDim.x + threadIdx.x;
    if (s >= HW) return;
#pragma unroll
    for (int a = 0; a < APL; a++) {
        float m = cls[(a*3 + 0)*HW + s];
        m = fmaxf(m, cls[(a*3 + 1)*HW + s]);
        m = fmaxf(m, cls[(a*3 + 2)*HW + s]);
        float sig = sigd(m);             // positive -> float bits order-preserving
        unsigned key = __float_as_uint(sig);
        g_key[s*APL + a] = key;
        atomicAdd(&g_hist[key >> 16], 1u);
    }
}

// ---------------- kernel 2: find level-1 threshold bin ----------------
__global__ void __launch_bounds__(1024) find_thr1() {
    __shared__ unsigned csum[1024];
    unsigned ssum = 0;
    int base = threadIdx.x * 64;
    for (int b = 0; b < 64; b++) ssum += g_hist[base + b];
    csum[threadIdx.x] = ssum;
    __syncthreads();
    if (threadIdx.x == 0) {
        unsigned acc = 0; int ch;
        for (ch = 1023; ch >= 0; ch--) {
            if (acc + csum[ch] >= (unsigned)KPRE) break;
            acc += csum[ch];
        }
        unsigned C1 = acc; int T = ch * 64;
        for (int b = 63; b >= 0; b--) {
            unsigned h = g_hist[ch*64 + b];
            if (C1 + h >= (unsigned)KPRE) { T = ch*64 + b; break; }
            C1 += h;
        }
        g_thr1 = T;
        g_k2 = KPRE - (int)C1;
    }
}

// ---------------- kernel 3: compact winners + boundary candidates ----------------
__global__ void compact1() {
    int i = blockIdx.x * blockDim.x + threadIdx.x;
    if (i >= NANCH) return;
    unsigned key = g_key[i];
    int bin = (int)(key >> 16);
    int T = g_thr1;
    if (bin > T) {
        int p = atomicAdd(&g_cntHi, 1);
        g_topk_idx[p] = i;
    } else if (bin == T) {
        int p = atomicAdd(&g_candCnt, 1);
        if (p < CAND_CAP) { g_cand_key[p] = key; g_cand_idx[p] = i; }
    }
}

// ---------------- kernel 4: level-2 refinement + exact tie-break ----------------
__global__ void __launch_bounds__(1024) level2() {
    __shared__ unsigned csum[1024];
    __shared__ int sT2, sk3;
    int nc = min(g_candCnt, CAND_CAP);
    int k2 = g_k2;
    for (int t = threadIdx.x; t < nc; t += 1024)
        atomicAdd(&g_hist2[g_cand_key[t] & 0xFFFFu], 1u);
    __syncthreads();
    unsigned ssum = 0; int base = threadIdx.x * 64;
    for (int b = 0; b < 64; b++) ssum += g_hist2[base + b];
    csum[threadIdx.x] = ssum;
    __syncthreads();
    if (threadIdx.x == 0) {
        unsigned acc = 0; int ch;
        for (ch = 1023; ch >= 0; ch--) {
            if (acc + csum[ch] >= (unsigned)k2) break;
            acc += csum[ch];
        }
        unsigned C1 = acc; int T = ch * 64;
        for (int b = 63; b >= 0; b--) {
            unsigned h = g_hist2[ch*64 + b];
            if (C1 + h >= (unsigned)k2) { T = ch*64 + b; break; }
            C1 += h;
        }
        sT2 = T; sk3 = k2 - (int)C1;
    }
    __syncthreads();
    int T2 = sT2;
    for (int t = threadIdx.x; t < nc; t += 1024) {
        int low = (int)(g_cand_key[t] & 0xFFFFu);
        if (low > T2) {
            int p = atomicAdd(&g_cntHi, 1);
            g_topk_idx[p] = g_cand_idx[t];
        } else if (low == T2) {
            int p = atomicAdd(&g_tieCnt, 1);
            if (p < TIE_CAP) g_tie[p] = g_cand_idx[t];
        }
    }
    __syncthreads();
    int m = min(g_tieCnt, TIE_CAP);
    int k3 = sk3;
    // exact-key ties: JAX top_k prefers smallest flat index
    for (int t = threadIdx.x; t < m; t += 1024) {
        int idx = g_tie[t];
        int rank = 0;
        for (int u = 0; u < m; u++) rank += (g_tie[u] < idx) ? 1 : 0;
        if (rank < k3) {
            int p = atomicAdd(&g_cntHi, 1);
            g_topk_idx[p] = idx;
        }
    }
}

// ---------------- kernel 4b: canonicalize top-k order (score desc, idx asc) ----------------
__global__ void __launch_bounds__(1024) sort_topk() {
    __shared__ unsigned long long sm[KPRE];
    for (int t = threadIdx.x; t < KPRE; t += 1024) {
        int idx = g_topk_idx[t];
        sm[t] = ((unsigned long long)g_key[idx] << 32) | (unsigned)(~(unsigned)idx);
    }
    __syncthreads();
    for (unsigned k = 2; k <= KPRE; k <<= 1) {
        for (unsigned j = k >> 1; j > 0; j >>= 1) {
            for (unsigned t = threadIdx.x; t < KPRE; t += 1024) {
                unsigned ixj = t ^ j;
                if (ixj > t) {
                    unsigned long long A = sm[t], B = sm[ixj];
                    if ((A < B) == ((t & k) == 0)) { sm[t] = B; sm[ixj] = A; }  // descending
                }
            }
            __syncthreads();
        }
    }
    for (int t = threadIdx.x; t < KPRE; t += 1024)
        g_topk_idx[t] = (int)(~(unsigned)(sm[t] & 0xFFFFFFFFu));
}

// ---------------- kernel 5: gather + decode the 4096 selected anchors ----------------
__global__ void decode_kernel(const float* __restrict__ cls, const float* __restrict__ bp,
                              const float* __restrict__ dirp, const float* __restrict__ priors) {
    int t = blockIdx.x * blockDim.x + threadIdx.x;
    if (t >= KPRE) return;
    int i = g_topk_idx[t];
    int s = i / APL, a = i - s * APL;
#pragma unroll
    for (int c = 0; c < 3; c++)
        g_sc[t*3 + c] = sigd(cls[(a*3 + c)*HW + s]);
    float dv0 = dirp[(a*2 + 0)*HW + s];
    float dv1 = dirp[(a*2 + 1)*HW + s];
    g_dirf[t] = (dv1 > dv0) ? 1.f : 0.f;   // argmax, first index on ties

    float dl[7], an[7];
#pragma unroll
    for (int k = 0; k < 7; k++) {
        dl[k] = bp[(a*7 + k)*HW + s];
        an[k] = priors[(size_t)i*7 + k];
    }
    // per-op IEEE rounding, same op order as reference (no FMA contraction)
    float za   = __fadd_rn(an[2], __fmul_rn(an[5], 0.5f));
    float diag = sqrtf(__fadd_rn(__fmul_rn(an[4], an[4]), __fmul_rn(an[3], an[3])));
    float xg = __fadd_rn(__fmul_rn(dl[0], diag), an[0]);
    float yg = __fadd_rn(__fmul_rn(dl[1], diag), an[1]);
    float zg = __fadd_rn(__fmul_rn(dl[2], an[5]), za);
    float wg = __fmul_rn(expf(dl[3]), an[3]);
    float lg = __fmul_rn(expf(dl[4]), an[4]);
    float hg = __fmul_rn(expf(dl[5]), an[5]);
    float rg = __fadd_rn(dl[6], an[6]);
    zg = __fsub_rn(zg, __fmul_rn(hg, 0.5f));
    g_box[t*7+0]=xg; g_box[t*7+1]=yg; g_box[t*7+2]=zg;
    g_box[t*7+3]=wg; g_box[t*7+4]=lg; g_box[t*7+5]=hg; g_box[t*7+6]=rg;
    g_xyxy[t] = make_float4(__fsub_rn(xg, __fmul_rn(wg, 0.5f)),
                            __fsub_rn(yg, __fmul_rn(lg, 0.5f)),
                            __fadd_rn(xg, __fmul_rn(wg, 0.5f)),
                            __fadd_rn(yg, __fmul_rn(lg, 0.5f)));
}

// ---------------- kernel 6: per-class bitonic sort (score desc, topk-pos asc) ----------------
__global__ void __launch_bounds__(1024) sort_class() {
    int c = blockIdx.x;
    __shared__ unsigned long long sm[KPRE];
    for (int t = threadIdx.x; t < KPRE; t += 1024) {
        float sc = g_sc[t*3 + c];
        sm[t] = ((unsigned long long)__float_as_uint(sc) << 32) | (unsigned)(~(unsigned)t);
    }
    __syncthreads();
    for (unsigned k = 2; k <= KPRE; k <<= 1) {
        for (unsigned j = k >> 1; j > 0; j >>= 1) {
            for (unsigned t = threadIdx.x; t < KPRE; t += 1024) {
                unsigned ixj = t ^ j;
                if (ixj > t) {
                    unsigned long long A = sm[t], B = sm[ixj];
                    if ((A < B) == ((t & k) == 0)) { sm[t] = B; sm[ixj] = A; }  // descending
                }
            }
            __syncthreads();
        }
    }
    for (int t = threadIdx.x; t < KPRE; t += 1024) {
        unsigned long long key = sm[t];
        int slot = (int)(~(unsigned)(key & 0xFFFFFFFFu));
        g_sorted_slot[c*KPRE + t] = slot;
        g_sorted_score[c*KPRE + t] = __uint_as_float((unsigned)(key >> 32));
        g_sxy[c*KPRE + t] = g_xyxy[slot];
    }
}

// ---------------- kernel 7: lazy greedy NMS (one block per class) ----------------
__global__ void __launch_bounds__(1024) nms_reduce() {
    int c = blockIdx.x;
    int tid = threadIdx.x;
    __shared__ unsigned long long remv[64];
    __shared__ unsigned long long validw[64];
    __shared__ int s_i;
    __shared__ float s_x1, s_y1, s_x2, s_y2, s_ar;

    // cache own 4 boxes in registers
    float4 bx[4]; float ar[4];
#pragma unroll
    for (int k = 0; k < 4; k++) {
        int j = tid + k * 1024;
        float4 b = g_sxy[c*KPRE + j];
        bx[k] = b;
        ar[k] = area_rn(b.x, b.y, b.z, b.w);
    }
    if (tid < 64) {
        remv[tid] = 0ull;
        unsigned long long w = 0ull;
#pragma unroll 8
        for (int b = 0; b < 64; b++)
            if (g_sorted_score[c*KPRE + tid*64 + b] > SCORE_THR) w |= 1ull << b;
        validw[tid] = w;
    }
    __syncthreads();

    int cnt = 0;
    int wd0 = 0;  // meaningful on thread 0 only
    while (true) {
        if (tid == 0) {
            int found = -1;
            for (int wd = wd0; wd < 64; wd++) {
                unsigned long long avail = validw[wd] & ~remv[wd];
                if (avail) { found = wd*64 + __ffsll((long long)avail) - 1; wd0 = wd; break; }
            }
            s_i = found;
            if (found >= 0) {
                remv[found >> 6] |= 1ull << (found & 63);
                g_kept_slot[c*MAXN + cnt]  = g_sorted_slot[c*KPRE + found];
                g_kept_score[c*MAXN + cnt] = g_sorted_score[c*KPRE + found];
                float4 b = g_sxy[c*KPRE + found];
                s_x1 = b.x; s_y1 = b.y; s_x2 = b.z; s_y2 = b.w;
                s_ar = area_rn(b.x, b.y, b.z, b.w);
            }
        }
        __syncthreads();
        int i = s_i;
        if (i < 0) break;
        float rx1 = s_x1, ry1 = s_y1, rx2 = s_x2, ry2 = s_y2, ra = s_ar;
#pragma unroll
        for (int k = 0; k < 4; k++) {
            int j = tid + k * 1024;
            if (j > i) {
                float xx1 = fmaxf(rx1, bx[k].x);
                float yy1 = fmaxf(ry1, bx[k].y);
                float xx2 = fminf(rx2, bx[k].z);
                float yy2 = fminf(ry2, bx[k].w);
                float w  = __fadd_rn(__fsub_rn(xx2, xx1), 1.f);
                float h2 = __fadd_rn(__fsub_rn(yy2, yy1), 1.f);
                if (w > 0.f && h2 > 0.f) {
                    float inter = __fmul_rn(w, h2);
                    float denom = __fsub_rn(__fadd_rn(ra, ar[k]), inter);
                    float iou = __fdiv_rn(inter, denom);
                    if (iou > NMS_THR) atomicOr(&remv[j >> 6], 1ull << (j & 63));
                }
            }
        }
        __syncthreads();
        cnt++;
        if (cnt >= MAXN) break;   // only top-500/class can reach the final output
    }
    if (tid == 0) g_kept_cnt[c] = cnt;
}

// ---------------- kernel 8: merge + final top-500 + output ----------------
__global__ void __launch_bounds__(1024) final_merge(float* __restrict__ out) {
    __shared__ unsigned long long sm[2048];
    for (int t = threadIdx.x; t < 2048; t += 1024) {
        unsigned long long key = 0ull;
        if (t < 3*MAXN) {
            int c = t / MAXN, pos = t % MAXN;
            if (pos < g_kept_cnt[c]) {
                float sc = g_kept_score[c*MAXN + pos];
                unsigned flat = (unsigned)(c*KPRE + pos);
                key = ((unsigned long long)__float_as_uint(sc) << 32) | (unsigned)(~flat);
            }
        }
        sm[t] = key;
    }
    __syncthreads();
    for (unsigned k = 2; k <= 2048; k <<= 1) {
        for (unsigned j = k >> 1; j > 0; j >>= 1) {
            for (unsigned t = threadIdx.x; t < 2048; t += 1024) {
                unsigned ixj = t ^ j;
                if (ixj > t) {
                    unsigned long long A = sm[t], B = sm[ixj];
                    if ((A < B) == ((t & k) == 0)) { sm[t] = B; sm[ixj] = A; }
                }
            }
            __syncthreads();
        }
    }
    for (int r = threadIdx.x; r < MAXN; r += 1024) {
        unsigned long long key = sm[r];
        if (key != 0ull) {
            float score = __uint_as_float((unsigned)(key >> 32));
            unsigned flat = ~(unsigned)(key & 0xFFFFFFFFu);
            int c = (int)(flat >> 12);
            int pos = (int)(flat & 4095u);
            int slot = g_kept_slot[c*MAXN + pos];
            float b[7];
#pragma unroll
            for (int k = 0; k < 7; k++) b[k] = g_box[slot*7 + k];
            float rr = b[6];
            float dir_rot = __fsub_rn(__fadd_rn(rr, PIH_F),
                                      __fmul_rn(floorf(__fadd_rn(rr, 0.5f)), PI_F));
            b[6] = __fadd_rn(__fsub_rn(dir_rot, PIH_F), __fmul_rn(PI_F, g_dirf[slot]));
#pragma unroll
            for (int k = 0; k < 7; k++) out[r*7 + k] = b[k];
            out[7*MAXN + r] = score;
            out[8*MAXN + r] = (float)c;
        } else {
#pragma unroll
            for (int k = 0; k < 7; k++) out[r*7 + k] = 0.f;
            out[7*MAXN + r] = 0.f;
            out[8*MAXN + r] = -1.f;
        }
    }
}

// ---------------- launch ----------------
extern "C" void kernel_launch(void* const* d_in, const int* in_sizes, int n_in,
                              void* d_out, int out_size) {
    const float* cls    = (const float*)d_in[0];
    const float* bp     = (const float*)d_in[1];
    const float* dirp   = (const float*)d_in[2];
    const float* priors = (const float*)d_in[3];
    float* out = (float*)d_out;

    zero_kernel<<<256, 256>>>();
    score_hist<<<(HW + 255) / 256, 256>>>(cls);
    find_thr1<<<1, 1024>>>();
    compact1<<<(NANCH + 255) / 256, 256>>>();
    level2<<<1, 1024>>>();
    sort_topk<<<1, 1024>>>();
    decode_kernel<<<(KPRE + 255) / 256, 256>>>(cls, bp, dirp, priors);
    sort_class<<<3, 1024>>>();
    nms_reduce<<<3, 1024>>>();
    final_merge<<<1, 1024>>>(out);
}